// round 15
// baseline (speedup 1.0000x reference)
#include <cuda_runtime.h>
#include <cuda_fp16.h>
#include <cstdint>

typedef uint32_t u32;

#define CL 8
#define NCTA 128
#define THREADS 512
#define T_LEN 512
#define SA 264                  // A row stride in halves (528 B)
#define MST 132                 // stage row stride in floats

// ---- smem byte offsets ----
#define OFF_A    0              // fp16 W plane, 128*528 = 67584
#define OFF_B    67584          // 4 tiles [G][p] fp16, 8448 each (row=batch, 528B stride)
#define OFF_ST   101376         // 2 groups x 16*132*4 = 8448 each
#define OFF_HST  118272         // h staging: 2 groups x 16 rows x 80B = 2560
#define OFF_MBAR 120832
#define SMEM_BYTES 120864

// ---- device scratch ----
__device__ __align__(16) __half g_Apack[CL][128*SA];   // [rank] fp16 W, [m][k] padded
__device__ float g_wih[CL*128];        // [(r*32+hid)*4+g]
__device__ float g_bias[CL*128];
__device__ float g_tsT[T_LEN*512];     // [t][b]
__device__ float g_part[CL*512];

// ---- asm helpers ----
__device__ __forceinline__ u32 smem_u32(const void* p){
    u32 a;
    asm("{ .reg .u64 t; cvta.to.shared.u64 t, %1; cvt.u32.u64 %0, t; }" : "=r"(a) : "l"(p));
    return a;
}
#define LDSM4(R, addr) \
    asm volatile("ldmatrix.sync.aligned.m8n8.x4.shared.b16 {%0,%1,%2,%3}, [%4];" \
        : "=r"((R)[0]), "=r"((R)[1]), "=r"((R)[2]), "=r"((R)[3]) : "r"(addr))
#define MBAR_INIT(addr, count) \
    asm volatile("mbarrier.init.shared.b64 [%0], %1;" :: "r"(addr), "r"(count) : "memory")
#define BAR_SYNC(id, n)   asm volatile("bar.sync %0, %1;"   :: "r"(id), "r"(n) : "memory")
#define BAR_ARRIVE(id, n) asm volatile("bar.arrive %0, %1;" :: "r"(id), "r"(n) : "memory")
__device__ __forceinline__ u32 mapa_r(u32 addr, u32 rank){
    u32 r; asm("mapa.shared::cluster.u32 %0, %1, %2;" : "=r"(r) : "r"(addr), "r"(rank)); return r;
}
#define STSC128(addr, v) \
    asm volatile("st.shared::cluster.v4.b32 [%0], {%1,%2,%3,%4};" \
        :: "r"(addr), "r"((v).x), "r"((v).y), "r"((v).z), "r"((v).w) : "memory")
#define MBAR_ARRIVE_REL(addr) \
    asm volatile("mbarrier.arrive.release.cluster.shared::cluster.b64 _, [%0];" \
                 :: "r"(addr) : "memory")
__device__ __forceinline__ void mbar_wait(u32 mbar, u32 parity){
    asm volatile(
        "{\n\t.reg .pred P;\n\t"
        "W_%=:\n\t"
        "mbarrier.try_wait.parity.acquire.cluster.shared::cta.b64 P, [%0], %1, 0x989680;\n\t"
        "@!P bra W_%=;\n\t}"
        :: "r"(mbar), "r"(parity) : "memory");
}
__device__ __forceinline__ void mma_f16(float* d, const u32* a, const u32* b){
    asm volatile(
        "mma.sync.aligned.m16n8k16.row.col.f32.f16.f16.f32 "
        "{%0,%1,%2,%3}, {%4,%5,%6,%7}, {%8,%9}, {%0,%1,%2,%3};"
        : "+f"(d[0]), "+f"(d[1]), "+f"(d[2]), "+f"(d[3])
        : "r"(a[0]), "r"(a[1]), "r"(a[2]), "r"(a[3]), "r"(b[0]), "r"(b[1]));
}
__device__ __forceinline__ float sigf(float x){
    float e = __expf(-x); return __fdividef(1.f, 1.f + e);
}
__device__ __forceinline__ float tanha(float x){
    float ax = fabsf(x);
    float e = __expf(-2.f*ax);
    float t = __fdividef(1.f - e, 1.f + e);
    return copysignf(t, x);
}

// ---- prep: W -> fp16 in padded [m][k] layout ----
__global__ void prep_kernel(const float* __restrict__ ts, const float* __restrict__ W_ih,
                            const float* __restrict__ W_hh, const float* __restrict__ b_ih,
                            const float* __restrict__ b_hh){
    int i0 = blockIdx.x*blockDim.x + threadIdx.x, stride = gridDim.x*blockDim.x;
    for (int idx = i0; idx < CL*128*256; idx += stride){
        int k = idx & 255, m = (idx>>8)&127, r = idx>>15;
        int hid = m>>2, g = m&3;
        float w = W_hh[(g*256 + r*32 + hid)*256 + k];
        g_Apack[r][m*SA + k] = __float2half_rn(w);
    }
    for (int idx = i0; idx < CL*128; idx += stride){
        int g = idx&3, hid = (idx>>2)&31, r = idx>>7;
        int j = g*256 + r*32 + hid;
        g_wih[idx]  = W_ih[j];
        g_bias[idx] = b_ih[j] + b_hh[j];
    }
    for (int idx = i0; idx < T_LEN*512; idx += stride){
        int b = idx & 511, t = idx >> 9;
        g_tsT[idx] = ts[b*T_LEN + t];
    }
}

__global__ void dummy_kernel(){}

// ---- main: cluster-8 LSTM, warp-specialized, DSMEM 16B-push exchange ----
__global__ void __launch_bounds__(THREADS, 1) __cluster_dims__(CL, 1, 1)
lstm_mma(const float* __restrict__ Wout){
    extern __shared__ char smem[];
    u32 sb = smem_u32(smem);
    int tid = threadIdx.x, wid = tid >> 5, lane = tid & 31;
    uint32_t rk; asm("mov.u32 %0, %%cluster_ctarank;" : "=r"(rk));
    int B0 = (blockIdx.x >> 3) * 32;

    // init: A -> smem, zero all 4 B tiles (h0 = 0), init mbarriers (count 256)
    {
        const uint4* src = (const uint4*)&g_Apack[rk][0];
        uint4* dst = (uint4*)smem;
        for (int i = tid; i < 67584/16; i += THREADS) dst[i] = src[i];
        uint4* bz = (uint4*)(smem + OFF_B);
        for (int i = tid; i < 33792/16; i += THREADS) bz[i] = make_uint4(0,0,0,0);
    }
    if (tid == 0){ MBAR_INIT(sb + OFF_MBAR, 256); MBAR_INIT(sb + OFF_MBAR + 8, 256); }
    __syncthreads();
    asm volatile("barrier.cluster.arrive.aligned;" ::: "memory");
    asm volatile("barrier.cluster.wait.aligned;"   ::: "memory");

    if (wid < 8){
        // ================= GEMM role (warps 0-7) =================
        int w = wid;
        int q = lane >> 3, r = lane & 7;
        u32 aA = sb + (u32)((w*16 + (q&1)*8 + r)*528 + (q>>1)*16);
        u32 bBase[2][2];
        #pragma unroll
        for (int G = 0; G < 2; ++G)
            #pragma unroll
            for (int p = 0; p < 2; ++p)
                bBase[G][p] = sb + OFF_B + (u32)((G*2+p)*8448)
                            + (u32)((((q>>1)*8 + r)*528) + (q&1)*16);
        int fg = lane >> 2, ft = lane & 3;
        int m0 = w*16 + fg, n0 = ft*2;

        for (int t = 0; t < T_LEN; ++t){
            int p = t & 1;
            #pragma unroll
            for (int G = 0; G < 2; ++G){
                BAR_SYNC(1 + G, 512);                 // B tile ready
                float acc0[4] = {0,0,0,0}, acc1[4] = {0,0,0,0};
                u32 bA = bBase[G][p];
                #pragma unroll
                for (int kt = 0; kt < 16; ++kt){
                    u32 ah[4], bh[4];
                    LDSM4(ah, aA + kt*32);
                    LDSM4(bh, bA + kt*32);
                    mma_f16(acc0, ah, bh);        // n 0-7
                    mma_f16(acc1, ah, bh + 2);    // n 8-15
                }
                float* stG = (float*)(smem + OFF_ST + G*8448);
                stG[n0*MST + m0]           = acc0[0];
                stG[(n0+1)*MST + m0]       = acc0[1];
                stG[n0*MST + m0 + 8]       = acc0[2];
                stG[(n0+1)*MST + m0 + 8]   = acc0[3];
                stG[(n0+8)*MST + m0]       = acc1[0];
                stG[(n0+9)*MST + m0]       = acc1[1];
                stG[(n0+8)*MST + m0 + 8]   = acc1[2];
                stG[(n0+9)*MST + m0 + 8]   = acc1[3];
                BAR_ARRIVE(3 + G, 512);               // stage ready
            }
        }
    } else {
        // ================= EXCH role (warps 8-15) =================
        int e = tid - 256;
        int hid = e & 31, bb = e >> 5;               // 2 batches: bb*2, bb*2+1
        int ghid = (int)rk*32 + hid;
        float4 wih = ((const float4*)g_wih )[rk*32 + hid];
        float4 bia = ((const float4*)g_bias)[rk*32 + hid];
        float creg[2][2] = {{0,0},{0,0}};
        float oacc[2][2] = {{0,0},{0,0}};

        // push role: warp (wid-8) serves rank wr; thread covers (row, chunk pair)
        int wr = wid - 8;
        u32 rdstB = mapa_r(sb + OFF_B + (u32)(rk*64), (u32)wr);
        u32 rmb0  = mapa_r(sb + OFF_MBAR,     (u32)wr);
        u32 rmb1  = mapa_r(sb + OFF_MBAR + 8, (u32)wr);
        int prow = lane & 15, pcp = lane >> 4;       // row 0-15, chunk-pair 0-1

        BAR_ARRIVE(1, 512); BAR_ARRIVE(2, 512);      // prime B_ready (tiles zeroed)

        for (int t = 0; t < T_LEN; ++t){
            int wp = t & 1, p1 = wp ^ 1;
            float wo = Wout[t*256 + ghid];
            float xv[2][2];
            #pragma unroll
            for (int G = 0; G < 2; ++G)
                #pragma unroll
                for (int j = 0; j < 2; ++j)
                    xv[G][j] = g_tsT[t*512 + B0 + G*16 + bb*2 + j];

            #pragma unroll
            for (int G = 0; G < 2; ++G){
                u32 mbar = sb + OFF_MBAR + G*8;
                BAR_SYNC(3 + G, 512);                 // stage ready
                const float* stG = (const float*)(smem + OFF_ST + G*8448);
                char* hstG = smem + OFF_HST + G*1280;
                #pragma unroll
                for (int j = 0; j < 2; ++j){
                    int b = bb*2 + j;
                    float4 gq = *(const float4*)(stG + b*MST + hid*4);
                    float x = xv[G][j];
                    float gi = gq.x + fmaf(x, wih.x, bia.x);
                    float gf = gq.y + fmaf(x, wih.y, bia.y);
                    float gg = gq.z + fmaf(x, wih.z, bia.z);
                    float go = gq.w + fmaf(x, wih.w, bia.w);
                    float c  = sigf(gf)*creg[G][j] + sigf(gi)*tanha(gg);
                    creg[G][j] = c;
                    float h  = sigf(go)*tanha(c);
                    oacc[G][j] = fmaf(h, wo, oacc[G][j]);
                    *(__half*)(hstG + b*80 + hid*2) = __float2half_rn(h);
                }
                if (t < T_LEN-1){
                    BAR_SYNC(6, 256);                 // hstage(G) ready (exch-only)
                    // push this CTA's 64B run into rank wr's B tile (G, p1)
                    uint4 v0 = *(const uint4*)(hstG + prow*80 + pcp*32);
                    uint4 v1 = *(const uint4*)(hstG + prow*80 + pcp*32 + 16);
                    u32 dst = rdstB + (u32)((G*2 + p1)*8448 + prow*528 + pcp*32);
                    STSC128(dst,      v0);
                    STSC128(dst + 16, v1);
                    MBAR_ARRIVE_REL(G == 0 ? rmb0 : rmb1);   // release own stores
                    mbar_wait(mbar, (u32)wp);         // all 256 arrives -> tile complete
                    BAR_ARRIVE(1 + G, 512);           // next B tile ready
                }
            }
        }
        // park oacc in stage smem for the epilogue
        {
            float* se = (float*)(smem + OFF_ST);
            se[(0*16 + bb*2 + 0)*33 + hid] = oacc[0][0];
            se[(0*16 + bb*2 + 1)*33 + hid] = oacc[0][1];
            se[(1*16 + bb*2 + 0)*33 + hid] = oacc[1][0];
            se[(1*16 + bb*2 + 1)*33 + hid] = oacc[1][1];
        }
    }

    // ---- epilogue ----
    __syncthreads();
    if (tid < 32){
        const float* se = (const float*)(smem + OFF_ST);
        float s = 0.f;
        for (int h2 = 0; h2 < 32; ++h2) s += se[tid*33 + h2];
        g_part[(size_t)rk*512 + B0 + tid] = s;
    }
    asm volatile("barrier.cluster.arrive.aligned;" ::: "memory");
    asm volatile("barrier.cluster.wait.aligned;"   ::: "memory");
}

// ---- finish ----
__global__ void finish_kernel(const float* __restrict__ b_out, float* __restrict__ out){
    int b = blockIdx.x * blockDim.x + threadIdx.x;
    if (b < 512){
        float s = b_out[0];
        #pragma unroll
        for (int r = 0; r < CL; ++r) s += g_part[r*512 + b];
        out[b] = s;
    }
}

extern "C" void kernel_launch(void* const* d_in, const int* in_sizes, int n_in,
                              void* d_out, int out_size){
    const float* ts    = (const float*)d_in[0];
    const float* W_ih  = (const float*)d_in[1];
    const float* W_hh  = (const float*)d_in[2];
    const float* b_ih  = (const float*)d_in[3];
    const float* b_hh  = (const float*)d_in[4];
    const float* W_out = (const float*)d_in[5];
    const float* b_out = (const float*)d_in[6];
    float* out = (float*)d_out;

    cudaFuncSetAttribute(lstm_mma, cudaFuncAttributeMaxDynamicSharedMemorySize, SMEM_BYTES);
    prep_kernel<<<256, 256>>>(ts, W_ih, W_hh, b_ih, b_hh);
    dummy_kernel<<<1, 32>>>();
    dummy_kernel<<<1, 32>>>();
    lstm_mma<<<NCTA, THREADS, SMEM_BYTES>>>(W_out);   // 16 clusters x 8 CTAs
    finish_kernel<<<2, 256>>>(b_out, out);
}

// round 16
// speedup vs baseline: 1.5653x; 1.5653x over previous
#include <cuda_runtime.h>
#include <cuda_fp16.h>
#include <cstdint>

typedef uint32_t u32;

#define CL 8
#define NCTA 128
#define THREADS 512
#define T_LEN 512
#define SA 264                  // A row stride in halves (528 B)
#define MST 132                 // stage row stride in floats

// ---- smem byte offsets ----
#define OFF_A   0               // single fp16 W plane, 128*528 = 67584
#define OFF_B   67584           // 4 tiles [G][p] single fp16 plane, 8448 each
#define OFF_ST  101376          // 2 groups x 16*132*4 = 8448 each
#define OFF_MBAR 118272
#define SMEM_BYTES 118304

// ---- device scratch ----
__device__ __align__(16) __half g_Apack[CL][128*SA];   // [rank] fp16 W, [m][k] padded
__device__ float g_wih[CL*128];        // [(r*32+hid)*4+g]
__device__ float g_bias[CL*128];
__device__ float g_tsT[T_LEN*512];     // [t][b]
__device__ __align__(16) __half g_hq[2][512*256];  // [parity][b][k] fp16 h
__device__ float g_part[CL*512];

// ---- asm helpers ----
__device__ __forceinline__ u32 smem_u32(const void* p){
    u32 a;
    asm("{ .reg .u64 t; cvta.to.shared.u64 t, %1; cvt.u32.u64 %0, t; }" : "=r"(a) : "l"(p));
    return a;
}
#define LDSM4(R, addr) \
    asm volatile("ldmatrix.sync.aligned.m8n8.x4.shared.b16 {%0,%1,%2,%3}, [%4];" \
        : "=r"((R)[0]), "=r"((R)[1]), "=r"((R)[2]), "=r"((R)[3]) : "r"(addr))
#define MBAR_INIT(addr, count) \
    asm volatile("mbarrier.init.shared.b64 [%0], %1;" :: "r"(addr), "r"(count) : "memory")
#define MBAR_ARRIVE_CLUSTER(addr, rank) \
    asm volatile("{\n\t.reg .b32 ra;\n\tmapa.shared::cluster.u32 ra, %0, %1;\n\t" \
                 "mbarrier.arrive.shared::cluster.b64 _, [ra];\n\t}" \
                 :: "r"(addr), "r"(rank) : "memory")
#define BAR_SYNC(id, n)   asm volatile("bar.sync %0, %1;"   :: "r"(id), "r"(n) : "memory")
#define BAR_ARRIVE(id, n) asm volatile("bar.arrive %0, %1;" :: "r"(id), "r"(n) : "memory")
__device__ __forceinline__ void mbar_wait(u32 mbar, u32 parity){
    asm volatile(
        "{\n\t.reg .pred P;\n\t"
        "W_%=:\n\t"
        "mbarrier.try_wait.parity.acquire.cluster.shared::cta.b64 P, [%0], %1, 0x989680;\n\t"
        "@!P bra W_%=;\n\t}"
        :: "r"(mbar), "r"(parity) : "memory");
}
__device__ __forceinline__ void mma_f16(float* d, const u32* a, const u32* b){
    asm volatile(
        "mma.sync.aligned.m16n8k16.row.col.f32.f16.f16.f32 "
        "{%0,%1,%2,%3}, {%4,%5,%6,%7}, {%8,%9}, {%0,%1,%2,%3};"
        : "+f"(d[0]), "+f"(d[1]), "+f"(d[2]), "+f"(d[3])
        : "r"(a[0]), "r"(a[1]), "r"(a[2]), "r"(a[3]), "r"(b[0]), "r"(b[1]));
}
__device__ __forceinline__ float sigf(float x){
    float e = __expf(-x); return __fdividef(1.f, 1.f + e);
}
__device__ __forceinline__ float tanha(float x){
    float ax = fabsf(x);
    float e = __expf(-2.f*ax);
    float t = __fdividef(1.f - e, 1.f + e);
    return copysignf(t, x);
}

// ---- prep: W -> fp16 in padded [m][k] layout ----
__global__ void prep_kernel(const float* __restrict__ ts, const float* __restrict__ W_ih,
                            const float* __restrict__ W_hh, const float* __restrict__ b_ih,
                            const float* __restrict__ b_hh){
    int i0 = blockIdx.x*blockDim.x + threadIdx.x, stride = gridDim.x*blockDim.x;
    for (int idx = i0; idx < CL*128*256; idx += stride){
        int k = idx & 255, m = (idx>>8)&127, r = idx>>15;
        int hid = m>>2, g = m&3;
        float w = W_hh[(g*256 + r*32 + hid)*256 + k];
        g_Apack[r][m*SA + k] = __float2half_rn(w);
    }
    for (int idx = i0; idx < CL*128; idx += stride){
        int g = idx&3, hid = (idx>>2)&31, r = idx>>7;
        int j = g*256 + r*32 + hid;
        g_wih[idx]  = W_ih[j];
        g_bias[idx] = b_ih[j] + b_hh[j];
    }
    for (int idx = i0; idx < T_LEN*512; idx += stride){
        int b = idx & 511, t = idx >> 9;
        g_tsT[idx] = ts[b*T_LEN + t];
    }
}

__global__ void dummy_kernel(){}

// ---- main: cluster-8 LSTM, GEMM warps + per-group exchange warp-halves ----
__global__ void __launch_bounds__(THREADS, 1) __cluster_dims__(CL, 1, 1)
lstm_mma(const float* __restrict__ Wout){
    extern __shared__ char smem[];
    u32 sb = smem_u32(smem);
    int tid = threadIdx.x, wid = tid >> 5, lane = tid & 31;
    uint32_t rk; asm("mov.u32 %0, %%cluster_ctarank;" : "=r"(rk));
    int B0 = (blockIdx.x >> 3) * 32;

    // init: A -> smem, zero all 4 B tiles (h0 = 0), init mbarriers (count 32)
    {
        const uint4* src = (const uint4*)&g_Apack[rk][0];
        uint4* dst = (uint4*)smem;
        for (int i = tid; i < 67584/16; i += THREADS) dst[i] = src[i];
        uint4* bz = (uint4*)(smem + OFF_B);
        for (int i = tid; i < 33792/16; i += THREADS) bz[i] = make_uint4(0,0,0,0);
    }
    if (tid == 0){ MBAR_INIT(sb + OFF_MBAR, 32); MBAR_INIT(sb + OFF_MBAR + 8, 32); }
    __syncthreads();
    asm volatile("barrier.cluster.arrive.aligned;" ::: "memory");
    asm volatile("barrier.cluster.wait.aligned;"   ::: "memory");

    if (wid < 8){
        // ================= GEMM role (warps 0-7) =================
        int w = wid;
        int q = lane >> 3, r = lane & 7;
        u32 aA = sb + (u32)((w*16 + (q&1)*8 + r)*528 + (q>>1)*16);
        u32 bBase[2][2];
        #pragma unroll
        for (int G = 0; G < 2; ++G)
            #pragma unroll
            for (int p = 0; p < 2; ++p)
                bBase[G][p] = sb + OFF_B + (u32)((G*2+p)*8448)
                            + (u32)((((q>>1)*8 + r)*528) + (q&1)*16);
        int fg = lane >> 2, ft = lane & 3;
        int m0 = w*16 + fg, n0 = ft*2;

        for (int t = 0; t < T_LEN; ++t){
            int p = t & 1;
            #pragma unroll
            for (int G = 0; G < 2; ++G){
                BAR_SYNC(1 + G, 384);                 // B tile ready (exch half G + gemm)
                float acc0[4] = {0,0,0,0}, acc1[4] = {0,0,0,0};
                u32 bA = bBase[G][p];
                #pragma unroll
                for (int kt = 0; kt < 16; ++kt){
                    u32 ah[4], bh[4];
                    LDSM4(ah, aA + kt*32);
                    LDSM4(bh, bA + kt*32);
                    mma_f16(acc0, ah, bh);        // n 0-7
                    mma_f16(acc1, ah, bh + 2);    // n 8-15
                }
                float* stG = (float*)(smem + OFF_ST + G*8448);
                stG[n0*MST + m0]           = acc0[0];
                stG[(n0+1)*MST + m0]       = acc0[1];
                stG[n0*MST + m0 + 8]       = acc0[2];
                stG[(n0+1)*MST + m0 + 8]   = acc0[3];
                stG[(n0+8)*MST + m0]       = acc1[0];
                stG[(n0+9)*MST + m0]       = acc1[1];
                stG[(n0+8)*MST + m0 + 8]   = acc1[2];
                stG[(n0+9)*MST + m0 + 8]   = acc1[3];
                BAR_ARRIVE(3 + G, 384);               // stage(G) ready
            }
        }
    } else {
        // ============ EXCH role: warps 8-11 -> G0, warps 12-15 -> G1 ============
        int e = tid - 256;
        int G = e >> 7;                              // group this half serves
        int f = e & 127;
        int hid = f & 31, bq = f >> 5;               // 4 batches: bq*4 .. +3
        int ghid = (int)rk*32 + hid;
        float4 wih = ((const float4*)g_wih )[rk*32 + hid];
        float4 bia = ((const float4*)g_bias)[rk*32 + hid];
        float creg[4] = {0,0,0,0};
        float oacc[4] = {0,0,0,0};
        int rn = f & 15, rks = f >> 4;               // rebuild: row, 64B slice (0..7)
        u32 mbar = sb + OFF_MBAR + G*8;

        BAR_ARRIVE(1 + G, 384);                      // prime B_ready (tiles zeroed)

        for (int t = 0; t < T_LEN; ++t){
            int wp = t & 1, p1 = wp ^ 1;
            float wo = Wout[t*256 + ghid];
            float xv[4];
            #pragma unroll
            for (int j = 0; j < 4; ++j)
                xv[j] = g_tsT[t*512 + B0 + G*16 + bq*4 + j];

            BAR_SYNC(3 + G, 384);                     // stage(G) ready
            const float* stG = (const float*)(smem + OFF_ST + G*8448);
            #pragma unroll
            for (int j = 0; j < 4; ++j){
                int b = bq*4 + j;
                float4 gq = *(const float4*)(stG + b*MST + hid*4);
                float x = xv[j];
                float gi = gq.x + fmaf(x, wih.x, bia.x);
                float gf = gq.y + fmaf(x, wih.y, bia.y);
                float gg = gq.z + fmaf(x, wih.z, bia.z);
                float go = gq.w + fmaf(x, wih.w, bia.w);
                float c  = sigf(gf)*creg[j] + sigf(gi)*tanha(gg);
                creg[j]  = c;
                float h  = sigf(go)*tanha(c);
                oacc[j]  = fmaf(h, wo, oacc[j]);
                g_hq[wp][(size_t)(B0 + G*16 + b)*256 + ghid] = __float2half_rn(h);
            }
            if (t < T_LEN-1){
                __syncwarp();                         // order warp's STGs before release
                if (lane == 0){
                    #pragma unroll
                    for (int dr = 0; dr < CL; ++dr) MBAR_ARRIVE_CLUSTER(mbar, dr);
                }
                mbar_wait(mbar, (u32)wp);             // 32 arrives: 4 warps x 8 ranks
                // rebuild: 64B straight copy per thread
                const uint4* src = (const uint4*)(g_hq[wp] + (size_t)(B0 + G*16 + rn)*256 + rks*32);
                uint4 v0 = __ldcg(src),   v1 = __ldcg(src+1);
                uint4 v2 = __ldcg(src+2), v3 = __ldcg(src+3);
                char* bt = smem + OFF_B + (G*2 + p1)*8448 + rn*528 + rks*64;
                *(uint4*)(bt)      = v0;
                *(uint4*)(bt + 16) = v1;
                *(uint4*)(bt + 32) = v2;
                *(uint4*)(bt + 48) = v3;
                BAR_ARRIVE(1 + G, 384);               // next B tile ready
            }
        }
        // park oacc in stage smem for the epilogue
        {
            float* se = (float*)(smem + OFF_ST);
            #pragma unroll
            for (int j = 0; j < 4; ++j)
                se[(G*16 + bq*4 + j)*33 + hid] = oacc[j];
        }
    }

    // ---- epilogue ----
    __syncthreads();
    if (tid < 32){
        const float* se = (const float*)(smem + OFF_ST);
        float s = 0.f;
        for (int h2 = 0; h2 < 32; ++h2) s += se[tid*33 + h2];
        g_part[(size_t)rk*512 + B0 + tid] = s;
    }
    asm volatile("barrier.cluster.arrive.aligned;" ::: "memory");
    asm volatile("barrier.cluster.wait.aligned;"   ::: "memory");
}

// ---- finish ----
__global__ void finish_kernel(const float* __restrict__ b_out, float* __restrict__ out){
    int b = blockIdx.x * blockDim.x + threadIdx.x;
    if (b < 512){
        float s = b_out[0];
        #pragma unroll
        for (int r = 0; r < CL; ++r) s += g_part[r*512 + b];
        out[b] = s;
    }
}

extern "C" void kernel_launch(void* const* d_in, const int* in_sizes, int n_in,
                              void* d_out, int out_size){
    const float* ts    = (const float*)d_in[0];
    const float* W_ih  = (const float*)d_in[1];
    const float* W_hh  = (const float*)d_in[2];
    const float* b_ih  = (const float*)d_in[3];
    const float* b_hh  = (const float*)d_in[4];
    const float* W_out = (const float*)d_in[5];
    const float* b_out = (const float*)d_in[6];
    float* out = (float*)d_out;

    cudaFuncSetAttribute(lstm_mma, cudaFuncAttributeMaxDynamicSharedMemorySize, SMEM_BYTES);
    prep_kernel<<<256, 256>>>(ts, W_ih, W_hh, b_ih, b_hh);
    dummy_kernel<<<1, 32>>>();
    dummy_kernel<<<1, 32>>>();
    lstm_mma<<<NCTA, THREADS, SMEM_BYTES>>>(W_out);   // 16 clusters x 8 CTAs
    finish_kernel<<<2, 256>>>(b_out, out);
}

// round 17
// speedup vs baseline: 3.1861x; 2.0354x over previous
#include <cuda_runtime.h>
#include <cuda_fp16.h>
#include <cstdint>

typedef uint32_t u32;

#define CL 4
#define NCTA 128
#define THREADS 512
#define T_LEN 512
#define SA 264                  // A row stride in halves (528 B)
#define MST 260                 // stage row stride in floats (conflict-free both sides)

// ---- smem byte offsets ----
#define OFF_A   0               // fp16 W plane, 256*528 = 135168
#define OFF_B   135168          // 4 tiles [G][p] fp16, 8 rows x 528 = 4224 each
#define OFF_ST  152064          // 2 groups x 8448 (8 rows x 260 floats = 8320 used)
#define OFF_MBAR 168960
#define SMEM_BYTES 168992

// ---- device scratch ----
__device__ __align__(16) __half g_Apack[CL][256*SA];   // [rank] fp16 W, [m][k] padded
__device__ float g_wih[CL*256];        // [(r*64+hid)*4+g]
__device__ float g_bias[CL*256];
__device__ float g_tsT[T_LEN*512];     // [t][b]
__device__ __align__(16) __half g_hq[2][512*256];  // [parity][b][k] fp16 h
__device__ float g_part[CL*512];

// ---- asm helpers ----
__device__ __forceinline__ u32 smem_u32(const void* p){
    u32 a;
    asm("{ .reg .u64 t; cvta.to.shared.u64 t, %1; cvt.u32.u64 %0, t; }" : "=r"(a) : "l"(p));
    return a;
}
#define LDSM4(R, addr) \
    asm volatile("ldmatrix.sync.aligned.m8n8.x4.shared.b16 {%0,%1,%2,%3}, [%4];" \
        : "=r"((R)[0]), "=r"((R)[1]), "=r"((R)[2]), "=r"((R)[3]) : "r"(addr))
#define MBAR_INIT(addr, count) \
    asm volatile("mbarrier.init.shared.b64 [%0], %1;" :: "r"(addr), "r"(count) : "memory")
#define MBAR_ARRIVE_CLUSTER(addr, rank) \
    asm volatile("{\n\t.reg .b32 ra;\n\tmapa.shared::cluster.u32 ra, %0, %1;\n\t" \
                 "mbarrier.arrive.shared::cluster.b64 _, [ra];\n\t}" \
                 :: "r"(addr), "r"(rank) : "memory")
#define BAR_SYNC(id, n)   asm volatile("bar.sync %0, %1;"   :: "r"(id), "r"(n) : "memory")
#define BAR_ARRIVE(id, n) asm volatile("bar.arrive %0, %1;" :: "r"(id), "r"(n) : "memory")
__device__ __forceinline__ void mbar_wait(u32 mbar, u32 parity){
    asm volatile(
        "{\n\t.reg .pred P;\n\t"
        "W_%=:\n\t"
        "mbarrier.try_wait.parity.acquire.cluster.shared::cta.b64 P, [%0], %1, 0x989680;\n\t"
        "@!P bra W_%=;\n\t}"
        :: "r"(mbar), "r"(parity) : "memory");
}
__device__ __forceinline__ void mma_f16(float* d, const u32* a, const u32* b){
    asm volatile(
        "mma.sync.aligned.m16n8k16.row.col.f32.f16.f16.f32 "
        "{%0,%1,%2,%3}, {%4,%5,%6,%7}, {%8,%9}, {%0,%1,%2,%3};"
        : "+f"(d[0]), "+f"(d[1]), "+f"(d[2]), "+f"(d[3])
        : "r"(a[0]), "r"(a[1]), "r"(a[2]), "r"(a[3]), "r"(b[0]), "r"(b[1]));
}
__device__ __forceinline__ float sigf(float x){
    float e = __expf(-x); return __fdividef(1.f, 1.f + e);
}
__device__ __forceinline__ float tanha(float x){
    float ax = fabsf(x);
    float e = __expf(-2.f*ax);
    float t = __fdividef(1.f - e, 1.f + e);
    return copysignf(t, x);
}

// ---- prep: W -> fp16 in padded [m][k] layout (m = hid_local*4 + gate) ----
__global__ void prep_kernel(const float* __restrict__ ts, const float* __restrict__ W_ih,
                            const float* __restrict__ W_hh, const float* __restrict__ b_ih,
                            const float* __restrict__ b_hh){
    int i0 = blockIdx.x*blockDim.x + threadIdx.x, stride = gridDim.x*blockDim.x;
    for (int idx = i0; idx < CL*256*256; idx += stride){
        int k = idx & 255, m = (idx>>8)&255, r = idx>>16;
        int hid = m>>2, g = m&3;
        float w = W_hh[(g*256 + r*64 + hid)*256 + k];
        g_Apack[r][m*SA + k] = __float2half_rn(w);
    }
    for (int idx = i0; idx < CL*256; idx += stride){
        int g = idx&3, hid = (idx>>2)&63, r = idx>>8;
        int j = g*256 + r*64 + hid;
        g_wih[idx]  = W_ih[j];
        g_bias[idx] = b_ih[j] + b_hh[j];
    }
    for (int idx = i0; idx < T_LEN*512; idx += stride){
        int b = idx & 511, t = idx >> 9;
        g_tsT[idx] = ts[b*T_LEN + t];
    }
}

__global__ void dummy_kernel(){}

// ---- main: cluster-4 LSTM, GEMM warps + per-group exchange warp-halves ----
__global__ void __launch_bounds__(THREADS, 1) __cluster_dims__(CL, 1, 1)
lstm_mma(const float* __restrict__ Wout){
    extern __shared__ char smem[];
    u32 sb = smem_u32(smem);
    int tid = threadIdx.x, wid = tid >> 5, lane = tid & 31;
    uint32_t rk; asm("mov.u32 %0, %%cluster_ctarank;" : "=r"(rk));
    int B0 = (blockIdx.x >> 2) * 16;

    // init: A -> smem (135KB), zero 4 B tiles (h0 = 0), init mbarriers (count 16)
    {
        const uint4* src = (const uint4*)&g_Apack[rk][0];
        uint4* dst = (uint4*)smem;
        for (int i = tid; i < 135168/16; i += THREADS) dst[i] = src[i];
        uint4* bz = (uint4*)(smem + OFF_B);
        for (int i = tid; i < 16896/16; i += THREADS) bz[i] = make_uint4(0,0,0,0);
    }
    if (tid == 0){ MBAR_INIT(sb + OFF_MBAR, 16); MBAR_INIT(sb + OFF_MBAR + 8, 16); }
    __syncthreads();
    asm volatile("barrier.cluster.arrive.aligned;" ::: "memory");
    asm volatile("barrier.cluster.wait.aligned;"   ::: "memory");

    if (wid < 8){
        // ================= GEMM role (warps 0-7): M rows [w*32, w*32+32) =================
        int w = wid;
        int q = lane >> 3, r = lane & 7;
        u32 aA0 = sb + (u32)((w*32 + (q&1)*8 + r)*528 + (q>>1)*16);
        u32 aA1 = aA0 + 16*528;
        u32 bBase[2][2];
        #pragma unroll
        for (int G = 0; G < 2; ++G)
            #pragma unroll
            for (int p = 0; p < 2; ++p)
                bBase[G][p] = sb + OFF_B + (u32)((G*2+p)*4224) + (u32)(r*528 + q*16);
        int fg = lane >> 2, ft = lane & 3;
        int m0 = w*32 + fg, n0 = ft*2;

        for (int t = 0; t < T_LEN; ++t){
            int p = t & 1;
            #pragma unroll
            for (int G = 0; G < 2; ++G){
                BAR_SYNC(1 + G, 384);                 // B tile ready
                float acc0[4] = {0,0,0,0}, acc1[4] = {0,0,0,0};
                u32 bA = bBase[G][p];
                #pragma unroll
                for (int kt2 = 0; kt2 < 8; ++kt2){    // 2 k-steps per iter
                    u32 a00[4], a01[4], a10[4], a11[4], bh[4];
                    LDSM4(a00, aA0 + kt2*64);         // m-tile0, kt even
                    LDSM4(a01, aA1 + kt2*64);         // m-tile1, kt even
                    LDSM4(a10, aA0 + kt2*64 + 32);    // m-tile0, kt odd
                    LDSM4(a11, aA1 + kt2*64 + 32);
                    LDSM4(bh,  bA  + kt2*64);         // covers both kt (4 k-chunks)
                    mma_f16(acc0, a00, bh);
                    mma_f16(acc1, a01, bh);
                    mma_f16(acc0, a10, bh + 2);
                    mma_f16(acc1, a11, bh + 2);
                }
                float* stG = (float*)(smem + OFF_ST + G*8448);
                stG[n0*MST + m0]            = acc0[0];
                stG[(n0+1)*MST + m0]        = acc0[1];
                stG[n0*MST + m0 + 8]        = acc0[2];
                stG[(n0+1)*MST + m0 + 8]    = acc0[3];
                stG[n0*MST + m0 + 16]       = acc1[0];
                stG[(n0+1)*MST + m0 + 16]   = acc1[1];
                stG[n0*MST + m0 + 24]       = acc1[2];
                stG[(n0+1)*MST + m0 + 24]   = acc1[3];
                BAR_ARRIVE(3 + G, 384);               // stage(G) ready
            }
        }
    } else {
        // ============ EXCH role: warps 8-11 -> G0, warps 12-15 -> G1 ============
        int e = tid - 256;
        int G = e >> 7;                              // group this half serves
        int f = e & 127;
        int hid = f & 63, bq = f >> 6;               // 4 batches: bq*4 .. +3
        int ghid = (int)rk*64 + hid;
        float4 wih = ((const float4*)g_wih )[rk*64 + hid];
        float4 bia = ((const float4*)g_bias)[rk*64 + hid];
        float creg[4] = {0,0,0,0};
        float oacc[4] = {0,0,0,0};
        int rn = f & 7, rks = f >> 3;                // rebuild: row (0-7), 32B slice (0-15)
        u32 mbar = sb + OFF_MBAR + G*8;

        BAR_ARRIVE(1 + G, 384);                      // prime B_ready (tiles zeroed)

        for (int t = 0; t < T_LEN; ++t){
            int wp = t & 1, p1 = wp ^ 1;
            float wo = Wout[t*256 + ghid];
            float xv[4];
            #pragma unroll
            for (int j = 0; j < 4; ++j)
                xv[j] = g_tsT[t*512 + B0 + G*8 + bq*4 + j];

            BAR_SYNC(3 + G, 384);                     // stage(G) ready
            const float* stG = (const float*)(smem + OFF_ST + G*8448);
            #pragma unroll
            for (int j = 0; j < 4; ++j){
                int b = bq*4 + j;
                float4 gq = *(const float4*)(stG + b*MST + hid*4);
                float x = xv[j];
                float gi = gq.x + fmaf(x, wih.x, bia.x);
                float gf = gq.y + fmaf(x, wih.y, bia.y);
                float gg = gq.z + fmaf(x, wih.z, bia.z);
                float go = gq.w + fmaf(x, wih.w, bia.w);
                float c  = sigf(gf)*creg[j] + sigf(gi)*tanha(gg);
                creg[j]  = c;
                float h  = sigf(go)*tanha(c);
                oacc[j]  = fmaf(h, wo, oacc[j]);
                g_hq[wp][(size_t)(B0 + G*8 + b)*256 + ghid] = __float2half_rn(h);
            }
            if (t < T_LEN-1){
                __syncwarp();                         // order warp's STGs before release
                if (lane == 0){
                    #pragma unroll
                    for (int dr = 0; dr < CL; ++dr) MBAR_ARRIVE_CLUSTER(mbar, dr);
                }
                mbar_wait(mbar, (u32)wp);             // 16 arrives: 4 warps x 4 ranks
                // rebuild: 32B straight copy per thread
                const uint4* src = (const uint4*)(g_hq[wp] + (size_t)(B0 + G*8 + rn)*256 + rks*16);
                uint4 v0 = __ldcg(src), v1 = __ldcg(src+1);
                char* bt = smem + OFF_B + (G*2 + p1)*4224 + rn*528 + rks*32;
                *(uint4*)(bt)      = v0;
                *(uint4*)(bt + 16) = v1;
                BAR_ARRIVE(1 + G, 384);               // next B tile ready
            }
        }
        // park oacc in stage smem for the epilogue
        {
            float* se = (float*)(smem + OFF_ST);
            #pragma unroll
            for (int j = 0; j < 4; ++j)
                se[(G*8 + bq*4 + j)*65 + hid] = oacc[j];
        }
    }

    // ---- epilogue ----
    __syncthreads();
    if (tid < 16){
        const float* se = (const float*)(smem + OFF_ST);
        float s = 0.f;
        for (int h2 = 0; h2 < 64; ++h2) s += se[tid*65 + h2];
        g_part[(size_t)rk*512 + B0 + tid] = s;
    }
    asm volatile("barrier.cluster.arrive.aligned;" ::: "memory");
    asm volatile("barrier.cluster.wait.aligned;"   ::: "memory");
}

// ---- finish ----
__global__ void finish_kernel(const float* __restrict__ b_out, float* __restrict__ out){
    int b = blockIdx.x * blockDim.x + threadIdx.x;
    if (b < 512){
        float s = b_out[0];
        #pragma unroll
        for (int r = 0; r < CL; ++r) s += g_part[r*512 + b];
        out[b] = s;
    }
}

extern "C" void kernel_launch(void* const* d_in, const int* in_sizes, int n_in,
                              void* d_out, int out_size){
    const float* ts    = (const float*)d_in[0];
    const float* W_ih  = (const float*)d_in[1];
    const float* W_hh  = (const float*)d_in[2];
    const float* b_ih  = (const float*)d_in[3];
    const float* b_hh  = (const float*)d_in[4];
    const float* W_out = (const float*)d_in[5];
    const float* b_out = (const float*)d_in[6];
    float* out = (float*)d_out;

    cudaFuncSetAttribute(lstm_mma, cudaFuncAttributeMaxDynamicSharedMemorySize, SMEM_BYTES);
    prep_kernel<<<256, 256>>>(ts, W_ih, W_hh, b_ih, b_hh);
    dummy_kernel<<<1, 32>>>();
    dummy_kernel<<<1, 32>>>();
    lstm_mma<<<NCTA, THREADS, SMEM_BYTES>>>(W_out);   // 32 clusters x 4 CTAs
    finish_kernel<<<2, 256>>>(b_out, out);
}